// round 7
// baseline (speedup 1.0000x reference)
#include <cuda_runtime.h>
#include <math.h>
#include <stdint.h>

#define BB  2
#define SSL 2048
#define DD  1024
#define HH  16
#define HDD 64
#define MSZ (BB*SSL)

// Scratch (allocation-free rule: device globals). All tf32 bit patterns.
__device__ uint32_t g_xt[MSZ*DD];    // X, dim-interleaved tf32
__device__ uint32_t g_wqt[DD*DD];    // Wq^T [n][k], k interleaved
__device__ uint32_t g_wkt[DD*DD];    // Wk^T [n][k], k interleaved
__device__ uint32_t g_q [MSZ*DD];    // 0.125*Q, dim-interleaved tf32
__device__ uint32_t g_kt[MSZ*DD];    // softplus(K), dim-interleaved tf32
__device__ uint32_t g_v [MSZ*DD];    // Q+K, natural dims, tf32

// ---------------------------------------------------------------------------
// helpers
// ---------------------------------------------------------------------------
__device__ __forceinline__ uint32_t f2tf32(float x) {
    uint32_t r;
    asm("cvt.rna.tf32.f32 %0, %1;" : "=r"(r) : "f"(x));
    return r;
}

__device__ __forceinline__ void mma_tf32(float c[4], const uint32_t a[4],
                                         uint32_t b0, uint32_t b1) {
    asm volatile(
        "mma.sync.aligned.m16n8k8.row.col.f32.tf32.tf32.f32 "
        "{%0,%1,%2,%3}, {%4,%5,%6,%7}, {%8,%9}, {%0,%1,%2,%3};"
        : "+f"(c[0]), "+f"(c[1]), "+f"(c[2]), "+f"(c[3])
        : "r"(a[0]), "r"(a[1]), "r"(a[2]), "r"(a[3]), "r"(b0), "r"(b1));
}

__device__ __forceinline__ float softplus_f(float x) {
    return (x > 15.0f) ? x : log1pf(__expf(x));
}

__device__ __forceinline__ void cpa16(void* s, const void* g) {
    uint32_t sa = (uint32_t)__cvta_generic_to_shared(s);
    asm volatile("cp.async.ca.shared.global [%0], [%1], 16;" :: "r"(sa), "l"(g));
}
#define CP_COMMIT() asm volatile("cp.async.commit_group;")
#define CP_WAIT0()  asm volatile("cp.async.wait_group 0;")

// ---------------------------------------------------------------------------
// Convert X -> tf32, dim-interleaved (within 8-groups: j -> 2*(j&3)+(j>>2))
// ---------------------------------------------------------------------------
__global__ __launch_bounds__(256) void conv_x(const float* __restrict__ X)
{
    int idx = blockIdx.x * 256 + threadIdx.x;     // float4 index
    float4 f = ((const float4*)X)[idx];
    int c4  = idx & (DD/4 - 1);
    int row = idx >> 8;                            // DD/4 == 256
    uint32_t* o = g_xt + (size_t)row*DD + 8*(c4>>1) + (c4&1);
    o[0] = f2tf32(f.x); o[2] = f2tf32(f.y);
    o[4] = f2tf32(f.z); o[6] = f2tf32(f.w);
}

// ---------------------------------------------------------------------------
// Convert W -> W^T tf32 with k-interleave. grid (32,32,2), block (32,8).
// ---------------------------------------------------------------------------
__global__ void conv_w(const float* __restrict__ Wq, const float* __restrict__ Wk)
{
    __shared__ float ts[32][33];
    const float*  W = blockIdx.z ? Wk : Wq;
    uint32_t*     o = blockIdx.z ? g_wkt : g_wqt;
    int k0 = blockIdx.y*32, n0 = blockIdx.x*32;
    int tx = threadIdx.x, ty = threadIdx.y;
    #pragma unroll
    for (int i = 0; i < 4; i++)
        ts[ty+8*i][tx] = W[(size_t)(k0+ty+8*i)*DD + n0+tx];
    __syncthreads();
    int kp = 8*(tx>>3) + 2*(tx&3) + ((tx&7)>>2);   // interleave within 8-group
    #pragma unroll
    for (int i = 0; i < 4; i++)
        o[(size_t)(n0+ty+8*i)*DD + k0 + kp] = f2tf32(ts[tx][ty+8*i]);
}

// ---------------------------------------------------------------------------
// Fused projection: Q and K on the same X tile, cp.async double-buffered,
// LDS.64 fragment loads (interleaved k). Epilogue writes g_q (scaled,
// interleaved), g_kt (softplus, interleaved), g_v (Q+K, natural).
// CTA 128m x 64n, k-tile 32, 8 warps 4m x 2n.
// ---------------------------------------------------------------------------
#define PX_STR 40
#define PW_STR 40
#define PX_BUF (128*PX_STR)
#define PW_BUF (64*PW_STR)
#define PROJ_SMEM ((2*PX_BUF + 4*PW_BUF)*4)

__global__ void __launch_bounds__(256, 2) proj_tc(
    const float* __restrict__ bq, const float* __restrict__ bk)
{
    extern __shared__ uint32_t psm[];
    uint32_t* XsB  = psm;                    // [2][128][40]
    uint32_t* WqsB = psm + 2*PX_BUF;         // [2][64][40]
    uint32_t* WksB = WqsB + 2*PW_BUF;        // [2][64][40]

    const int m0 = blockIdx.y * 128;
    const int n0 = blockIdx.x * 64;
    const int t    = threadIdx.x;
    const int warp = t >> 5;
    const int lane = t & 31;
    const int lq   = lane & 3;
    const int lr   = lane >> 2;
    const int wm = (warp >> 1) * 32;
    const int wn = (warp & 1) * 32;

    const int xr = t >> 1, xc = t & 1;       // X: 128 rows x 8 chunks
    const int wr = t >> 2, wc = t & 3;       // W: 64 rows x 8 chunks

    float accq[2][4][4] = {};
    float acck[2][4][4] = {};

    {   // tile 0 -> buffer 0
        #pragma unroll
        for (int j = 0; j < 4; j++) {
            int ch = xc + 2*j;
            cpa16(&XsB[xr*PX_STR + 4*ch], g_xt + (size_t)(m0+xr)*DD + 4*ch);
        }
        #pragma unroll
        for (int j = 0; j < 2; j++) {
            int ch = wc + 4*j;
            cpa16(&WqsB[wr*PW_STR + 4*ch], g_wqt + (size_t)(n0+wr)*DD + 4*ch);
            cpa16(&WksB[wr*PW_STR + 4*ch], g_wkt + (size_t)(n0+wr)*DD + 4*ch);
        }
        CP_COMMIT();
    }
    CP_WAIT0();
    __syncthreads();

    for (int it = 0; it < DD/32; it++) {
        const int buf = it & 1;
        uint32_t* Xs  = XsB  + buf*PX_BUF;
        uint32_t* Wqs = WqsB + buf*PW_BUF;
        uint32_t* Wks = WksB + buf*PW_BUF;
        const bool more = (it + 1) < DD/32;

        if (more) {
            int k0 = (it+1)*32;
            uint32_t* Xn  = XsB  + (buf^1)*PX_BUF;
            uint32_t* Wqn = WqsB + (buf^1)*PW_BUF;
            uint32_t* Wkn = WksB + (buf^1)*PW_BUF;
            #pragma unroll
            for (int j = 0; j < 4; j++) {
                int ch = xc + 2*j;
                cpa16(&Xn[xr*PX_STR + 4*ch], g_xt + (size_t)(m0+xr)*DD + k0 + 4*ch);
            }
            #pragma unroll
            for (int j = 0; j < 2; j++) {
                int ch = wc + 4*j;
                cpa16(&Wqn[wr*PW_STR + 4*ch], g_wqt + (size_t)(n0+wr)*DD + k0 + 4*ch);
                cpa16(&Wkn[wr*PW_STR + 4*ch], g_wkt + (size_t)(n0+wr)*DD + k0 + 4*ch);
            }
            CP_COMMIT();
        }

        #pragma unroll
        for (int ks = 0; ks < 4; ks++) {
            int kb = ks * 8;
            uint32_t a[2][4];
            #pragma unroll
            for (int mt = 0; mt < 2; mt++) {
                int ar = wm + 16*mt + lr;
                uint2 a02 = *(const uint2*)&Xs[ar*PX_STR + kb + 2*lq];
                uint2 a13 = *(const uint2*)&Xs[(ar+8)*PX_STR + kb + 2*lq];
                a[mt][0] = a02.x; a[mt][1] = a13.x;
                a[mt][2] = a02.y; a[mt][3] = a13.y;
            }
            #pragma unroll
            for (int nt = 0; nt < 4; nt++) {
                int row = wn + 8*nt + lr;
                uint2 bqf = *(const uint2*)&Wqs[row*PW_STR + kb + 2*lq];
                uint2 bkf = *(const uint2*)&Wks[row*PW_STR + kb + 2*lq];
                #pragma unroll
                for (int mt = 0; mt < 2; mt++) {
                    mma_tf32(accq[mt][nt], a[mt], bqf.x, bqf.y);
                    mma_tf32(acck[mt][nt], a[mt], bkf.x, bkf.y);
                }
            }
        }
        CP_WAIT0();
        __syncthreads();
    }

    // epilogue
    #pragma unroll
    for (int nt = 0; nt < 4; nt++) {
        int c = n0 + wn + 8*nt + 2*lq;
        float bqx = bq[c], bqy = bq[c+1];
        float bkx = bk[c], bky = bk[c+1];
        int cb = c & ~7, j = c & 7;
        int j0 = 2*(j&3) + (j>>2);
        int j1 = 2*((j+1)&3) + ((j+1)>>2);
        #pragma unroll
        for (int mt = 0; mt < 2; mt++) {
            #pragma unroll
            for (int half = 0; half < 2; half++) {
                int r = m0 + wm + 16*mt + lr + 8*half;
                float qx = accq[mt][nt][2*half+0] + bqx;
                float qy = accq[mt][nt][2*half+1] + bqy;
                float kx = acck[mt][nt][2*half+0] + bkx;
                float ky = acck[mt][nt][2*half+1] + bky;
                size_t off = (size_t)r * DD;
                g_q [off + cb + j0] = f2tf32(0.125f*qx);
                g_q [off + cb + j1] = f2tf32(0.125f*qy);
                g_kt[off + cb + j0] = f2tf32(softplus_f(kx));
                g_kt[off + cb + j1] = f2tf32(softplus_f(ky));
                *(uint2*)&g_v[off + c] = make_uint2(f2tf32(qx+kx), f2tf32(qy+ky));
            }
        }
    }
}

// ---------------------------------------------------------------------------
// Flash attention v4: Q-tile 256, 256 threads (8 warps, warp tile 32x64).
// cp.async double-buffered K/V; LDS.64 fragment loads in S-phase
// (dim-interleaved Q/K); no-max softmax (p = exp(s), masked rows p=1);
// deferred l reduction. One __syncthreads per key tile.
// ---------------------------------------------------------------------------
#define AQ_STR 72
#define AK_STR 72
#define AV_STR 72
#define AP_STR 68
#define KBUF (64*AK_STR)
#define VBUF (64*AV_STR)
#define SMEM_ATTN ((256*AQ_STR + 2*KBUF + 2*VBUF + 256*AP_STR)*4)

__global__ void __launch_bounds__(256, 1) attn_tc(
    const int* __restrict__ amask, float* __restrict__ out)
{
    extern __shared__ uint32_t smu[];
    uint32_t* Qs  = smu;                    // [256][AQ_STR]
    uint32_t* KsB = Qs  + 256*AQ_STR;       // [2][64][AK_STR]
    uint32_t* VsB = KsB + 2*KBUF;           // [2][64][AV_STR]
    uint32_t* Ps  = VsB + 2*VBUF;           // [256][AP_STR]

    const int qt = blockIdx.x, h = blockIdx.y, b = blockIdx.z;
    const int t    = threadIdx.x;
    const int warp = t >> 5;
    const int lane = t & 31;
    const int lq   = lane & 3;
    const int lr   = lane >> 2;
    const int wm   = warp * 32;
    const int krow = t >> 2, kv = t & 3;    // K/V loader: 64 rows x 4 chunks

    {   // Q tile (16 chunks/row, 1 row per thread) + K/V tile 0
        const uint32_t* qg = g_q + ((size_t)(b*SSL + qt*256 + t))*DD + h*HDD;
        #pragma unroll
        for (int c = 0; c < 16; c++)
            cpa16(&Qs[t*AQ_STR + 4*c], qg + 4*c);
        size_t base = ((size_t)(b*SSL + krow))*DD + h*HDD;
        #pragma unroll
        for (int j = 0; j < 4; j++) {
            int c = kv + 4*j;
            cpa16(&KsB[krow*AK_STR + 4*c], g_kt + base + 4*c);
            cpa16(&VsB[krow*AV_STR + 4*c], g_v  + base + 4*c);
        }
        CP_COMMIT();
    }
    bool mflag[2][2];
    #pragma unroll
    for (int mt = 0; mt < 2; mt++) {
        mflag[mt][0] = (amask[b*SSL + qt*256 + wm + 16*mt + lr] == 0);
        mflag[mt][1] = (amask[b*SSL + qt*256 + wm + 16*mt + 8 + lr] == 0);
    }

    float tl[2][2] = {{0.0f,0.0f},{0.0f,0.0f}};   // partial l sums
    float accO[2][8][4] = {};
    CP_WAIT0();
    __syncthreads();

    for (int it = 0; it < SSL/64; it++) {
        const int buf = it & 1;
        uint32_t* Ks = KsB + buf*KBUF;
        uint32_t* Vs = VsB + buf*VBUF;

        if (it + 1 < SSL/64) {   // async prefetch next K/V tile
            uint32_t* Kn = KsB + (buf^1)*KBUF;
            uint32_t* Vn = VsB + (buf^1)*VBUF;
            size_t base = ((size_t)(b*SSL + (it+1)*64 + krow))*DD + h*HDD;
            #pragma unroll
            for (int j = 0; j < 4; j++) {
                int c = kv + 4*j;
                cpa16(&Kn[krow*AK_STR + 4*c], g_kt + base + 4*c);
                cpa16(&Vn[krow*AV_STR + 4*c], g_v  + base + 4*c);
            }
            CP_COMMIT();
        }

        // ---- S = (Q/8) @ K^T : warp computes 32x64 (LDS.64 frags) ----
        float accS[2][8][4] = {};
        #pragma unroll
        for (int ks = 0; ks < 8; ks++) {
            int kb = ks * 8;
            uint32_t a[2][4];
            #pragma unroll
            for (int mt = 0; mt < 2; mt++) {
                int ar = wm + 16*mt + lr;
                uint2 a02 = *(const uint2*)&Qs[ar*AQ_STR + kb + 2*lq];
                uint2 a13 = *(const uint2*)&Qs[(ar+8)*AQ_STR + kb + 2*lq];
                a[mt][0] = a02.x; a[mt][1] = a13.x;
                a[mt][2] = a02.y; a[mt][3] = a13.y;
            }
            #pragma unroll
            for (int nt = 0; nt < 8; nt++) {
                uint2 bb = *(const uint2*)&Ks[(8*nt+lr)*AK_STR + kb + 2*lq];
                mma_tf32(accS[0][nt], a[0], bb.x, bb.y);
                mma_tf32(accS[1][nt], a[1], bb.x, bb.y);
            }
        }

        // ---- softmax without running max: p = exp(s); masked rows p = 1 ----
        #pragma unroll
        for (int mt = 0; mt < 2; mt++) {
            const bool mA = mflag[mt][0], mB = mflag[mt][1];
            int ra = wm + 16*mt + lr, rb = ra + 8;
            float s0 = 0.0f, s1 = 0.0f;
            #pragma unroll
            for (int nt = 0; nt < 8; nt++) {
                float p00 = mA ? 1.0f : __expf(accS[mt][nt][0]);
                float p01 = mA ? 1.0f : __expf(accS[mt][nt][1]);
                float p10 = mB ? 1.0f : __expf(accS[mt][nt][2]);
                float p11 = mB ? 1.0f : __expf(accS[mt][nt][3]);
                s0 += p00 + p01;
                s1 += p10 + p11;
                *(uint2*)&Ps[ra*AP_STR + 8*nt + 2*lq] =
                    make_uint2(__float_as_uint(p00), __float_as_uint(p01));
                *(uint2*)&Ps[rb*AP_STR + 8*nt + 2*lq] =
                    make_uint2(__float_as_uint(p10), __float_as_uint(p11));
            }
            tl[mt][0] += s0;
            tl[mt][1] += s1;
        }
        __syncwarp();   // Ps rows owned by this warp

        // ---- O += P @ V ----
        #pragma unroll
        for (int ks = 0; ks < 8; ks++) {
            int kb = ks * 8;
            uint32_t a[2][4];
            #pragma unroll
            for (int mt = 0; mt < 2; mt++) {
                int ar = wm + 16*mt + lr;
                a[mt][0] = Ps[ar*AP_STR + kb + lq];
                a[mt][1] = Ps[(ar+8)*AP_STR + kb + lq];
                a[mt][2] = Ps[ar*AP_STR + kb + 4 + lq];
                a[mt][3] = Ps[(ar+8)*AP_STR + kb + 4 + lq];
            }
            #pragma unroll
            for (int nt = 0; nt < 8; nt++) {
                int bc = 8*nt + lr;
                uint32_t b0 = Vs[(kb + lq)*AV_STR + bc];
                uint32_t b1 = Vs[(kb + 4 + lq)*AV_STR + bc];
                mma_tf32(accO[0][nt], a[0], b0, b1);
                mma_tf32(accO[1][nt], a[1], b0, b1);
            }
        }
        CP_WAIT0();
        __syncthreads();
    }

    // ---- epilogue: reduce l across quad, write O / l ----
    #pragma unroll
    for (int mt = 0; mt < 2; mt++) {
        #pragma unroll
        for (int half = 0; half < 2; half++) {
            float v = tl[mt][half];
            v += __shfl_xor_sync(0xffffffffu, v, 1);
            v += __shfl_xor_sync(0xffffffffu, v, 2);
            tl[mt][half] = v;
        }
    }
    #pragma unroll
    for (int mt = 0; mt < 2; mt++) {
        int ra = wm + 16*mt + lr, rb = ra + 8;
        float li0 = 1.0f / tl[mt][0], li1 = 1.0f / tl[mt][1];
        size_t row0 = (size_t)(b*SSL + qt*256 + ra) * DD + h*HDD;
        size_t row1 = (size_t)(b*SSL + qt*256 + rb) * DD + h*HDD;
        #pragma unroll
        for (int nt = 0; nt < 8; nt++) {
            int col = 8*nt + 2*lq;
            *(float2*)(out + row0 + col) =
                make_float2(accO[mt][nt][0]*li0, accO[mt][nt][1]*li0);
            *(float2*)(out + row1 + col) =
                make_float2(accO[mt][nt][2]*li1, accO[mt][nt][3]*li1);
        }
    }
}

// ---------------------------------------------------------------------------
extern "C" void kernel_launch(void* const* d_in, const int* in_sizes, int n_in,
                              void* d_out, int out_size)
{
    const float* X     = (const float*)d_in[0];
    const int*   amask = (const int*)  d_in[1];
    const float* Wq    = (const float*)d_in[2];
    const float* bq    = (const float*)d_in[3];
    const float* Wk    = (const float*)d_in[4];
    const float* bk    = (const float*)d_in[5];
    float*       out   = (float*)d_out;

    cudaFuncSetAttribute(proj_tc,
                         cudaFuncAttributeMaxDynamicSharedMemorySize, PROJ_SMEM);
    cudaFuncSetAttribute(attn_tc,
                         cudaFuncAttributeMaxDynamicSharedMemorySize, SMEM_ATTN);

    conv_x<<<(MSZ*DD/4)/256, 256>>>(X);
    conv_w<<<dim3(32, 32, 2), dim3(32, 8)>>>(Wq, Wk);
    proj_tc<<<dim3(DD/64, MSZ/128), 256, PROJ_SMEM>>>(bq, bk);
    attn_tc<<<dim3(SSL/256, HH, BB), 256, SMEM_ATTN>>>(amask, out);
}

// round 8
// speedup vs baseline: 1.1044x; 1.1044x over previous
#include <cuda_runtime.h>
#include <math.h>
#include <stdint.h>

#define BB  2
#define SSL 2048
#define DD  1024
#define HH  16
#define HDD 64
#define MSZ (BB*SSL)

// Scratch (device globals). tf32 bit patterns.
// g_q : 0.125*Q, dim-interleaved within 8-groups (j -> 2*(j&3)+(j>>2))
// g_kt: softplus(K), dim-interleaved
// g_v : Q+K, natural dim order
__device__ uint32_t g_q [MSZ*DD];
__device__ uint32_t g_kt[MSZ*DD];
__device__ uint32_t g_v [MSZ*DD];

// ---------------------------------------------------------------------------
// helpers
// ---------------------------------------------------------------------------
__device__ __forceinline__ uint32_t f2tf32(float x) {
    uint32_t r;
    asm("cvt.rna.tf32.f32 %0, %1;" : "=r"(r) : "f"(x));
    return r;
}

__device__ __forceinline__ void mma_tf32(float c[4], const uint32_t a[4],
                                         uint32_t b0, uint32_t b1) {
    asm volatile(
        "mma.sync.aligned.m16n8k8.row.col.f32.tf32.tf32.f32 "
        "{%0,%1,%2,%3}, {%4,%5,%6,%7}, {%8,%9}, {%0,%1,%2,%3};"
        : "+f"(c[0]), "+f"(c[1]), "+f"(c[2]), "+f"(c[3])
        : "r"(a[0]), "r"(a[1]), "r"(a[2]), "r"(a[3]), "r"(b0), "r"(b1));
}

__device__ __forceinline__ float softplus_f(float x) {
    return (x > 15.0f) ? x : log1pf(__expf(x));
}

__device__ __forceinline__ void cpa16(void* s, const void* g) {
    uint32_t sa = (uint32_t)__cvta_generic_to_shared(s);
    asm volatile("cp.async.ca.shared.global [%0], [%1], 16;" :: "r"(sa), "l"(g));
}
#define CP_COMMIT() asm volatile("cp.async.commit_group;")
#define CP_WAIT0()  asm volatile("cp.async.wait_group 0;")

// ---------------------------------------------------------------------------
// Fused projection (r6 body): Q and K on the same X tile; epilogue writes
// g_q (0.125 scale, interleaved tf32), g_kt (softplus, interleaved tf32),
// g_v (Q+K, natural tf32). CTA 128m x 64n, k-tile 32, double-buffered smem.
// ---------------------------------------------------------------------------
#define XS_STR 36
#define WS_STR 72
#define XS_BUF (128*XS_STR)
#define WS_BUF (32*WS_STR)
#define PROJ_SMEM ((2*XS_BUF + 4*WS_BUF)*4)

__global__ void __launch_bounds__(256, 2) proj_tc(
    const float* __restrict__ X,
    const float* __restrict__ Wq, const float* __restrict__ bq,
    const float* __restrict__ Wk, const float* __restrict__ bk)
{
    extern __shared__ uint32_t psm[];
    uint32_t* XsB  = psm;
    uint32_t* WqsB = psm + 2*XS_BUF;
    uint32_t* WksB = WqsB + 2*WS_BUF;

    const int m0 = blockIdx.y * 128;
    const int n0 = blockIdx.x * 64;
    const int t    = threadIdx.x;
    const int warp = t >> 5;
    const int lane = t & 31;
    const int lq   = lane & 3;
    const int lr   = lane >> 2;
    const int wm = (warp >> 1) * 32;
    const int wn = (warp & 1) * 32;

    const int xr = t >> 1;
    const int xcb = (t & 1) * 4;
    const int wr = t >> 3;
    const int wcb = t & 7;

    float accq[2][4][4] = {};
    float acck[2][4][4] = {};

    {
        const float* xp = X + (size_t)(m0 + xr) * DD;
        #pragma unroll
        for (int j = 0; j < 4; j++) {
            int c = xcb + j;
            float4 f = *(const float4*)(xp + 4*c);
            *(uint4*)&XsB[xr*XS_STR + 4*c] =
                make_uint4(f2tf32(f.x), f2tf32(f.y), f2tf32(f.z), f2tf32(f.w));
        }
        const float* wqp = Wq + (size_t)wr * DD + n0;
        const float* wkp = Wk + (size_t)wr * DD + n0;
        #pragma unroll
        for (int j = 0; j < 2; j++) {
            int c = wcb + 8*j;
            float4 fq = *(const float4*)(wqp + 4*c);
            *(uint4*)&WqsB[wr*WS_STR + 4*c] =
                make_uint4(f2tf32(fq.x), f2tf32(fq.y), f2tf32(fq.z), f2tf32(fq.w));
            float4 fk = *(const float4*)(wkp + 4*c);
            *(uint4*)&WksB[wr*WS_STR + 4*c] =
                make_uint4(f2tf32(fk.x), f2tf32(fk.y), f2tf32(fk.z), f2tf32(fk.w));
        }
    }
    __syncthreads();

    for (int k0 = 0; k0 < DD; k0 += 32) {
        const int buf = (k0 >> 5) & 1;
        uint32_t* Xs  = XsB  + buf*XS_BUF;
        uint32_t* Wqs = WqsB + buf*WS_BUF;
        uint32_t* Wks = WksB + buf*WS_BUF;
        const bool more = (k0 + 32) < DD;

        float4 xst[4], wqst[2], wkst[2];
        if (more) {
            const float* xp = X + (size_t)(m0 + xr) * DD + k0 + 32;
            #pragma unroll
            for (int j = 0; j < 4; j++)
                xst[j] = *(const float4*)(xp + 4*(xcb + j));
            const float* wqp = Wq + (size_t)(k0 + 32 + wr) * DD + n0;
            const float* wkp = Wk + (size_t)(k0 + 32 + wr) * DD + n0;
            #pragma unroll
            for (int j = 0; j < 2; j++) {
                wqst[j] = *(const float4*)(wqp + 4*(wcb + 8*j));
                wkst[j] = *(const float4*)(wkp + 4*(wcb + 8*j));
            }
        }

        #pragma unroll
        for (int ks = 0; ks < 4; ks++) {
            int kb = ks * 8;
            uint32_t a[2][4];
            #pragma unroll
            for (int mt = 0; mt < 2; mt++) {
                int ar = wm + 16*mt + lr;
                a[mt][0] = Xs[ar*XS_STR + kb + lq];
                a[mt][1] = Xs[(ar+8)*XS_STR + kb + lq];
                a[mt][2] = Xs[ar*XS_STR + kb + lq + 4];
                a[mt][3] = Xs[(ar+8)*XS_STR + kb + lq + 4];
            }
            #pragma unroll
            for (int nt = 0; nt < 4; nt++) {
                int bc = wn + 8*nt + lr;
                uint32_t q0 = Wqs[(kb + lq)*WS_STR + bc];
                uint32_t q1 = Wqs[(kb + 4 + lq)*WS_STR + bc];
                uint32_t k0r = Wks[(kb + lq)*WS_STR + bc];
                uint32_t k1r = Wks[(kb + 4 + lq)*WS_STR + bc];
                #pragma unroll
                for (int mt = 0; mt < 2; mt++) {
                    mma_tf32(accq[mt][nt], a[mt], q0, q1);
                    mma_tf32(acck[mt][nt], a[mt], k0r, k1r);
                }
            }
        }

        if (more) {
            uint32_t* Xn  = XsB  + (buf^1)*XS_BUF;
            uint32_t* Wqn = WqsB + (buf^1)*WS_BUF;
            uint32_t* Wkn = WksB + (buf^1)*WS_BUF;
            #pragma unroll
            for (int j = 0; j < 4; j++) {
                float4 f = xst[j];
                *(uint4*)&Xn[xr*XS_STR + 4*(xcb + j)] =
                    make_uint4(f2tf32(f.x), f2tf32(f.y), f2tf32(f.z), f2tf32(f.w));
            }
            #pragma unroll
            for (int j = 0; j < 2; j++) {
                float4 fq = wqst[j];
                *(uint4*)&Wqn[wr*WS_STR + 4*(wcb + 8*j)] =
                    make_uint4(f2tf32(fq.x), f2tf32(fq.y), f2tf32(fq.z), f2tf32(fq.w));
                float4 fk = wkst[j];
                *(uint4*)&Wkn[wr*WS_STR + 4*(wcb + 8*j)] =
                    make_uint4(f2tf32(fk.x), f2tf32(fk.y), f2tf32(fk.z), f2tf32(fk.w));
            }
        }
        __syncthreads();
    }

    // epilogue: g_q (scaled, interleaved), g_kt (softplus, interleaved),
    // g_v (natural), all tf32 bits
    #pragma unroll
    for (int nt = 0; nt < 4; nt++) {
        int c = n0 + wn + 8*nt + 2*lq;
        float bqx = bq[c], bqy = bq[c+1];
        float bkx = bk[c], bky = bk[c+1];
        int cb = c & ~7, j = c & 7;
        int j0 = 2*(j&3) + (j>>2);
        int j1 = 2*((j+1)&3) + ((j+1)>>2);
        #pragma unroll
        for (int mt = 0; mt < 2; mt++) {
            #pragma unroll
            for (int half = 0; half < 2; half++) {
                int r = m0 + wm + 16*mt + lr + 8*half;
                float qx = accq[mt][nt][2*half+0] + bqx;
                float qy = accq[mt][nt][2*half+1] + bqy;
                float kx = acck[mt][nt][2*half+0] + bkx;
                float ky = acck[mt][nt][2*half+1] + bky;
                size_t off = (size_t)r * DD;
                g_q [off + cb + j0] = f2tf32(0.125f*qx);
                g_q [off + cb + j1] = f2tf32(0.125f*qy);
                g_kt[off + cb + j0] = f2tf32(softplus_f(kx));
                g_kt[off + cb + j1] = f2tf32(softplus_f(ky));
                *(uint2*)&g_v[off + c] = make_uint2(f2tf32(qx+kx), f2tf32(qy+ky));
            }
        }
    }
}

// ---------------------------------------------------------------------------
// Flash attention v5: Q-tile 128, 256 threads (8 warps, warp tile 16x64),
// 2 CTAs/SM (16 warps/SM). Q-fragments persistent in registers (loaded once
// from interleaved global, LDG.64). K/V double-buffered via cp.async.
// Streamed no-max softmax (2 halves, accS = 16 regs). One sync per tile.
// Query-axis mask -> row p=1 (uniform softmax, matches reference).
// ---------------------------------------------------------------------------
#define AK_STR 72
#define AV_STR 72
#define AP_STR 68
#define KBUF (64*AK_STR)
#define VBUF (64*AV_STR)
#define SMEM_ATTN ((2*KBUF + 2*VBUF + 128*AP_STR)*4)

__global__ void __launch_bounds__(256, 2) attn_tc(
    const int* __restrict__ amask, float* __restrict__ out)
{
    extern __shared__ uint32_t smu[];
    uint32_t* KsB = smu;                  // [2][64][AK_STR] interleaved dims
    uint32_t* VsB = KsB + 2*KBUF;         // [2][64][AV_STR] natural dims
    uint32_t* Ps  = VsB + 2*VBUF;         // [128][AP_STR]

    const int qt = blockIdx.x, h = blockIdx.y, b = blockIdx.z;
    const int t    = threadIdx.x;
    const int warp = t >> 5;
    const int lane = t & 31;
    const int lq   = lane & 3;
    const int lr   = lane >> 2;
    const int r0 = warp*16 + lr, r1 = r0 + 8;
    const int krow = t >> 2, kv = t & 3;   // K/V loader: 64 rows x 4 chunks

    {   // K/V tile 0 -> buffer 0 (async)
        size_t base = ((size_t)(b*SSL + krow))*DD + h*HDD;
        #pragma unroll
        for (int j = 0; j < 4; j++) {
            int c = kv + 4*j;
            cpa16(&KsB[krow*AK_STR + 4*c], g_kt + base + 4*c);
            cpa16(&VsB[krow*AV_STR + 4*c], g_v  + base + 4*c);
        }
        CP_COMMIT();
    }

    // Q fragments: persistent across all key tiles. Interleaved global ->
    // LDG.64 gives (k=8ks+lq, k=8ks+lq+4) adjacent.
    uint32_t aq[8][4];
    {
        const uint32_t* q0p = g_q + ((size_t)(b*SSL + qt*128 + r0))*DD + h*HDD;
        const uint32_t* q1p = g_q + ((size_t)(b*SSL + qt*128 + r1))*DD + h*HDD;
        #pragma unroll
        for (int ks = 0; ks < 8; ks++) {
            uint2 u0 = *(const uint2*)(q0p + 8*ks + 2*lq);
            uint2 u1 = *(const uint2*)(q1p + 8*ks + 2*lq);
            aq[ks][0] = u0.x; aq[ks][1] = u1.x;
            aq[ks][2] = u0.y; aq[ks][3] = u1.y;
        }
    }
    const bool mA = (amask[b*SSL + qt*128 + r0] == 0);
    const bool mB = (amask[b*SSL + qt*128 + r1] == 0);

    float tl0 = 0.0f, tl1 = 0.0f;
    float accO[8][4] = {};
    CP_WAIT0();
    __syncthreads();

    for (int it = 0; it < SSL/64; it++) {
        const int buf = it & 1;
        uint32_t* Ks = KsB + buf*KBUF;
        uint32_t* Vs = VsB + buf*VBUF;

        if (it + 1 < SSL/64) {   // async prefetch next tile into buf^1
            uint32_t* Kn = KsB + (buf^1)*KBUF;
            uint32_t* Vn = VsB + (buf^1)*VBUF;
            size_t base = ((size_t)(b*SSL + (it+1)*64 + krow))*DD + h*HDD;
            #pragma unroll
            for (int j = 0; j < 4; j++) {
                int c = kv + 4*j;
                cpa16(&Kn[krow*AK_STR + 4*c], g_kt + base + 4*c);
                cpa16(&Vn[krow*AV_STR + 4*c], g_v  + base + 4*c);
            }
            CP_COMMIT();
        }

        // ---- S + softmax, streamed in 2 halves of 4 key-blocks ----
        #pragma unroll
        for (int half = 0; half < 2; half++) {
            float accS[4][4] = {};
            #pragma unroll
            for (int ks = 0; ks < 8; ks++) {
                int kb = ks * 8;
                #pragma unroll
                for (int j = 0; j < 4; j++) {
                    int key0 = 8*(4*half + j) + lr;
                    uint2 bb = *(const uint2*)&Ks[key0*AK_STR + kb + 2*lq];
                    mma_tf32(accS[j], aq[ks], bb.x, bb.y);
                }
            }
            #pragma unroll
            for (int j = 0; j < 4; j++) {
                int nt = 4*half + j;
                float p00 = mA ? 1.0f : __expf(accS[j][0]);
                float p01 = mA ? 1.0f : __expf(accS[j][1]);
                float p10 = mB ? 1.0f : __expf(accS[j][2]);
                float p11 = mB ? 1.0f : __expf(accS[j][3]);
                tl0 += p00 + p01;
                tl1 += p10 + p11;
                *(uint2*)&Ps[r0*AP_STR + 8*nt + 2*lq] =
                    make_uint2(__float_as_uint(p00), __float_as_uint(p01));
                *(uint2*)&Ps[r1*AP_STR + 8*nt + 2*lq] =
                    make_uint2(__float_as_uint(p10), __float_as_uint(p11));
            }
        }
        __syncwarp();   // Ps rows owned and read by this warp only

        // ---- O += P @ V ----
        #pragma unroll
        for (int ks = 0; ks < 8; ks++) {
            int kb = ks * 8;
            uint32_t a[4];
            a[0] = Ps[r0*AP_STR + kb + lq];
            a[1] = Ps[r1*AP_STR + kb + lq];
            a[2] = Ps[r0*AP_STR + kb + 4 + lq];
            a[3] = Ps[r1*AP_STR + kb + 4 + lq];
            #pragma unroll
            for (int nt = 0; nt < 8; nt++) {
                int bc = 8*nt + lr;
                uint32_t b0 = Vs[(kb + lq)*AV_STR + bc];
                uint32_t b1 = Vs[(kb + 4 + lq)*AV_STR + bc];
                mma_tf32(accO[nt], a, b0, b1);
            }
        }
        CP_WAIT0();
        __syncthreads();
    }

    // ---- epilogue: reduce l across quad, write O / l ----
    tl0 += __shfl_xor_sync(0xffffffffu, tl0, 1);
    tl0 += __shfl_xor_sync(0xffffffffu, tl0, 2);
    tl1 += __shfl_xor_sync(0xffffffffu, tl1, 1);
    tl1 += __shfl_xor_sync(0xffffffffu, tl1, 2);
    float li0 = 1.0f / tl0, li1 = 1.0f / tl1;
    size_t row0 = (size_t)(b*SSL + qt*128 + r0) * DD + h*HDD;
    size_t row1 = (size_t)(b*SSL + qt*128 + r1) * DD + h*HDD;
    #pragma unroll
    for (int nt = 0; nt < 8; nt++) {
        int col = 8*nt + 2*lq;
        *(float2*)(out + row0 + col) = make_float2(accO[nt][0]*li0, accO[nt][1]*li0);
        *(float2*)(out + row1 + col) = make_float2(accO[nt][2]*li1, accO[nt][3]*li1);
    }
}

// ---------------------------------------------------------------------------
extern "C" void kernel_launch(void* const* d_in, const int* in_sizes, int n_in,
                              void* d_out, int out_size)
{
    const float* X     = (const float*)d_in[0];
    const int*   amask = (const int*)  d_in[1];
    const float* Wq    = (const float*)d_in[2];
    const float* bq    = (const float*)d_in[3];
    const float* Wk    = (const float*)d_in[4];
    const float* bk    = (const float*)d_in[5];
    float*       out   = (float*)d_out;

    cudaFuncSetAttribute(proj_tc,
                         cudaFuncAttributeMaxDynamicSharedMemorySize, PROJ_SMEM);
    cudaFuncSetAttribute(attn_tc,
                         cudaFuncAttributeMaxDynamicSharedMemorySize, SMEM_ATTN);

    proj_tc<<<dim3(DD/64, MSZ/128), 256, PROJ_SMEM>>>(X, Wq, bq, Wk, bk);
    attn_tc<<<dim3(SSL/128, HH, BB), 256, SMEM_ATTN>>>(amask, out);
}